// round 1
// baseline (speedup 1.0000x reference)
#include <cuda_runtime.h>

// out[n,d] = mean_f( x[n,f]*W[f,d] + b[f,d] )  =  (x@W)[n,d]/256 + mean_f(b[f,d])
// N=8192, F=256, D=64.  All inputs finite -> nan_to_num is a no-op.

typedef unsigned long long u64t;

#define NROWS 8192
#define NF    256
#define ND    64
#define ROWS_PER_BLOCK 32
#define THREADS 64
#define NBLOCKS (NROWS / ROWS_PER_BLOCK)   // 256

// dynamic smem layout (floats): W [256*64] | mb [64] | scratch [64 float4 = 256]
#define SMEM_FLOATS (NF * ND + ND + 256)
#define SMEM_BYTES  (SMEM_FLOATS * 4)

__device__ __forceinline__ u64t fma2(u64t a, u64t b, u64t c) {
    u64t d;
    asm("fma.rn.f32x2 %0, %1, %2, %3;" : "=l"(d) : "l"(a), "l"(b), "l"(c));
    return d;
}
__device__ __forceinline__ u64t pack2(float x, float y) {
    u64t d;
    asm("mov.b64 %0, {%1, %2};" : "=l"(d) : "f"(x), "f"(y));
    return d;
}

__global__ void __launch_bounds__(THREADS, 3)
nanembed_kernel(const float* __restrict__ x,
                const float* __restrict__ W,
                const float* __restrict__ b,
                float* __restrict__ out)
{
    extern __shared__ float smem[];
    float* Ws = smem;                       // 16384 floats
    float* mb = smem + NF * ND;             // 64 floats
    float4* sc = (float4*)(smem + NF * ND + ND);  // 64 float4 scratch

    const int tid = threadIdx.x;

    // ---- stage W into smem (64 KB), coalesced float4 ----
    {
        const float4* W4  = (const float4*)W;
        float4*       Ws4 = (float4*)Ws;
        #pragma unroll
        for (int i = 0; i < (NF * ND / 4) / THREADS; ++i)
            Ws4[tid + i * THREADS] = W4[tid + i * THREADS];
    }

    // ---- compute mb[d] = mean_f b[f][d]  (redundant per block, L2-resident) ----
    {
        const int qd = tid & 15;      // which d-quad (d = qd*4 .. qd*4+3)
        const int ch = tid >> 4;      // which f-chunk of 64
        const float4* b4 = (const float4*)b;   // [256][16] quads
        float4 s = make_float4(0.f, 0.f, 0.f, 0.f);
        #pragma unroll 8
        for (int f = 0; f < 64; ++f) {
            float4 v = b4[(ch * 64 + f) * 16 + qd];
            s.x += v.x; s.y += v.y; s.z += v.z; s.w += v.w;
        }
        sc[tid] = s;
        __syncthreads();
        if (tid < 16) {
            float4 s0 = sc[tid], s1 = sc[16 + tid], s2 = sc[32 + tid], s3 = sc[48 + tid];
            float4 m;
            const float inv = 1.f / 256.f;
            m.x = (s0.x + s1.x + s2.x + s3.x) * inv;
            m.y = (s0.y + s1.y + s2.y + s3.y) * inv;
            m.z = (s0.z + s1.z + s2.z + s3.z) * inv;
            m.w = (s0.w + s1.w + s2.w + s3.w) * inv;
            ((float4*)mb)[tid] = m;
        }
        __syncthreads();
    }

    // ---- main GEMM: each thread owns 4 rows x 8 output columns ----
    const int warp = tid >> 5;
    const int lane = tid & 31;
    const int dg   = lane & 7;    // d-group: columns dg*8 .. dg*8+7
    const int rg   = lane >> 3;   // row-group within warp
    const int d0   = dg * 8;
    const int rbase = blockIdx.x * ROWS_PER_BLOCK + warp * 16 + rg;

    const float* xp0 = x + (size_t)(rbase +  0) * NF;
    const float* xp1 = x + (size_t)(rbase +  4) * NF;
    const float* xp2 = x + (size_t)(rbase +  8) * NF;
    const float* xp3 = x + (size_t)(rbase + 12) * NF;

    u64t acc[4][4];   // [row][d-pair], packed f32x2 (all-zero bits == {0.f,0.f})
    #pragma unroll
    for (int i = 0; i < 4; ++i)
        #pragma unroll
        for (int j = 0; j < 4; ++j)
            acc[i][j] = 0ull;

    #pragma unroll 2
    for (int f4 = 0; f4 < NF / 4; ++f4) {
        const int f = f4 * 4;
        float xa0[4], xa1[4], xa2[4], xa3[4];
        *(float4*)xa0 = *(const float4*)(xp0 + f);
        *(float4*)xa1 = *(const float4*)(xp1 + f);
        *(float4*)xa2 = *(const float4*)(xp2 + f);
        *(float4*)xa3 = *(const float4*)(xp3 + f);

        #pragma unroll
        for (int j = 0; j < 4; ++j) {
            const ulonglong2* wp = (const ulonglong2*)&Ws[(f + j) * ND + d0];
            ulonglong2 wA = wp[0];   // d0..d3 as two f32x2
            ulonglong2 wB = wp[1];   // d4..d7 as two f32x2

            u64t xb0 = pack2(xa0[j], xa0[j]);
            acc[0][0] = fma2(xb0, wA.x, acc[0][0]);
            acc[0][1] = fma2(xb0, wA.y, acc[0][1]);
            acc[0][2] = fma2(xb0, wB.x, acc[0][2]);
            acc[0][3] = fma2(xb0, wB.y, acc[0][3]);

            u64t xb1 = pack2(xa1[j], xa1[j]);
            acc[1][0] = fma2(xb1, wA.x, acc[1][0]);
            acc[1][1] = fma2(xb1, wA.y, acc[1][1]);
            acc[1][2] = fma2(xb1, wB.x, acc[1][2]);
            acc[1][3] = fma2(xb1, wB.y, acc[1][3]);

            u64t xb2 = pack2(xa2[j], xa2[j]);
            acc[2][0] = fma2(xb2, wA.x, acc[2][0]);
            acc[2][1] = fma2(xb2, wA.y, acc[2][1]);
            acc[2][2] = fma2(xb2, wB.x, acc[2][2]);
            acc[2][3] = fma2(xb2, wB.y, acc[2][3]);

            u64t xb3 = pack2(xa3[j], xa3[j]);
            acc[3][0] = fma2(xb3, wA.x, acc[3][0]);
            acc[3][1] = fma2(xb3, wA.y, acc[3][1]);
            acc[3][2] = fma2(xb3, wB.x, acc[3][2]);
            acc[3][3] = fma2(xb3, wB.y, acc[3][3]);
        }
    }

    // ---- epilogue: out = acc/256 + mb ----
    const u64t cinv = pack2(1.f / 256.f, 1.f / 256.f);
    const ulonglong2* mbp = (const ulonglong2*)&mb[d0];
    const ulonglong2 m01 = mbp[0];
    const ulonglong2 m23 = mbp[1];

    #pragma unroll
    for (int i = 0; i < 4; ++i) {
        const int r = rbase + 4 * i;
        u64t r0 = fma2(acc[i][0], cinv, m01.x);
        u64t r1 = fma2(acc[i][1], cinv, m01.y);
        u64t r2 = fma2(acc[i][2], cinv, m23.x);
        u64t r3 = fma2(acc[i][3], cinv, m23.y);
        ulonglong2* op = (ulonglong2*)&out[(size_t)r * ND + d0];
        op[0] = make_ulonglong2(r0, r1);
        op[1] = make_ulonglong2(r2, r3);
    }
}

extern "C" void kernel_launch(void* const* d_in, const int* in_sizes, int n_in,
                              void* d_out, int out_size)
{
    const float* x = (const float*)d_in[0];
    const float* W = (const float*)d_in[1];
    const float* b = (const float*)d_in[2];
    float* out = (float*)d_out;

    cudaFuncSetAttribute(nanembed_kernel,
                         cudaFuncAttributeMaxDynamicSharedMemorySize, SMEM_BYTES);
    nanembed_kernel<<<NBLOCKS, THREADS, SMEM_BYTES>>>(x, W, b, out);
}

// round 2
// speedup vs baseline: 1.4320x; 1.4320x over previous
#include <cuda_runtime.h>

// out[n,d] = mean_f( x[n,f]*W[f,d] + b[f,d] )  =  (x@W)[n,d]/256 + mean_f(b[f,d])
// N=8192, F=256, D=64.  All inputs finite -> nan_to_num is a no-op.
//
// Block: 256 threads = 4 f-quarters x (8 d-groups x 8 row-slots).
// Each thread: 4 rows x 8 cols (cols = [dg*4, dg*4+4) U [32+dg*4, 32+dg*4+4)),
// reducing over its 64-element f-quarter. Quarter partials combined in smem.

typedef unsigned long long u64t;

#define NROWS 8192
#define NF    256
#define ND    64
#define ROWS_PER_BLOCK 32
#define THREADS 256
#define NBLOCKS (NROWS / ROWS_PER_BLOCK)   // 256

// smem floats: Ws[256*64] | red[3*32*64] | mb[64]
#define WS_FLOATS   (NF * ND)        // 16384
#define RED_FLOATS  (3 * ROWS_PER_BLOCK * ND)  // 6144
#define SMEM_FLOATS (WS_FLOATS + RED_FLOATS + ND)
#define SMEM_BYTES  (SMEM_FLOATS * 4)  // 90368

__device__ __forceinline__ u64t fma2(u64t a, u64t b, u64t c) {
    u64t d;
    asm("fma.rn.f32x2 %0, %1, %2, %3;" : "=l"(d) : "l"(a), "l"(b), "l"(c));
    return d;
}
__device__ __forceinline__ u64t add2(u64t a, u64t b) {
    u64t d;
    asm("add.rn.f32x2 %0, %1, %2;" : "=l"(d) : "l"(a), "l"(b));
    return d;
}
__device__ __forceinline__ u64t pack2(float x, float y) {
    u64t d;
    asm("mov.b64 %0, {%1, %2};" : "=l"(d) : "f"(x), "f"(y));
    return d;
}

__global__ void __launch_bounds__(THREADS, 2)
nanembed_kernel(const float* __restrict__ x,
                const float* __restrict__ W,
                const float* __restrict__ b,
                float* __restrict__ out)
{
    extern __shared__ float smem[];
    float* Ws  = smem;                         // 16384 floats
    float* red = smem + WS_FLOATS;             // 6144 floats (also scratch for mb)
    float* mb  = smem + WS_FLOATS + RED_FLOATS;// 64 floats
    float4* sc = (float4*)red;                 // 256 float4 scratch (pre-mainloop only)

    const int tid = threadIdx.x;

    // ---- stage W into smem (64 KB), coalesced float4 ----
    {
        const float4* W4  = (const float4*)W;
        float4*       Ws4 = (float4*)Ws;
        #pragma unroll
        for (int i = 0; i < (WS_FLOATS / 4) / THREADS; ++i)
            Ws4[tid + i * THREADS] = W4[tid + i * THREADS];
    }

    // ---- mb[d] = mean_f b[f][d] (redundant per block; b is L2-resident) ----
    {
        const int qd = tid & 15;      // d-quad index
        const int fr = tid >> 4;      // f-group (16 groups of 16)
        const float4* b4 = (const float4*)b;   // [256][16] quads
        float4 s = make_float4(0.f, 0.f, 0.f, 0.f);
        #pragma unroll
        for (int k = 0; k < 16; ++k) {
            float4 v = b4[(fr * 16 + k) * 16 + qd];
            s.x += v.x; s.y += v.y; s.z += v.z; s.w += v.w;
        }
        sc[tid] = s;
    }
    __syncthreads();
    if (tid < 16) {
        float4 m = make_float4(0.f, 0.f, 0.f, 0.f);
        #pragma unroll
        for (int g = 0; g < 16; ++g) {
            float4 v = sc[tid + 16 * g];
            m.x += v.x; m.y += v.y; m.z += v.z; m.w += v.w;
        }
        const float inv = 1.f / 256.f;
        m.x *= inv; m.y *= inv; m.z *= inv; m.w *= inv;
        ((float4*)mb)[tid] = m;
    }
    __syncthreads();

    // ---- thread mapping ----
    const int fq   = tid >> 6;          // f-quarter 0..3
    const int t    = tid & 63;
    const int dg   = t & 7;             // d-group
    const int slot = t >> 3;            // row slot 0..7
    const int dA   = dg * 4;            // first column quad
    const int dB   = 32 + dg * 4;       // second column quad
    const int rloc = slot * 4;          // local row base
    const int rbase = blockIdx.x * ROWS_PER_BLOCK + rloc;

    const float* xq = x + (size_t)rbase * NF + fq * 64;
    const float* Wq = Ws + fq * 64 * ND;

    u64t acc[4][4];   // [row][pair]: pairs 0,1 -> dA..dA+3 ; 2,3 -> dB..dB+3
    #pragma unroll
    for (int i = 0; i < 4; ++i)
        #pragma unroll
        for (int j = 0; j < 4; ++j)
            acc[i][j] = 0ull;

    #pragma unroll 4
    for (int f4 = 0; f4 < 16; ++f4) {
        float xa0[4], xa1[4], xa2[4], xa3[4];
        *(float4*)xa0 = *(const float4*)(xq + 0 * NF + f4 * 4);
        *(float4*)xa1 = *(const float4*)(xq + 1 * NF + f4 * 4);
        *(float4*)xa2 = *(const float4*)(xq + 2 * NF + f4 * 4);
        *(float4*)xa3 = *(const float4*)(xq + 3 * NF + f4 * 4);

        #pragma unroll
        for (int j = 0; j < 4; ++j) {
            const float* wrow = Wq + (f4 * 4 + j) * ND;
            ulonglong2 wA = *(const ulonglong2*)(wrow + dA);  // conflict-free
            ulonglong2 wB = *(const ulonglong2*)(wrow + dB);  // conflict-free

            u64t xb0 = pack2(xa0[j], xa0[j]);
            acc[0][0] = fma2(xb0, wA.x, acc[0][0]);
            acc[0][1] = fma2(xb0, wA.y, acc[0][1]);
            acc[0][2] = fma2(xb0, wB.x, acc[0][2]);
            acc[0][3] = fma2(xb0, wB.y, acc[0][3]);

            u64t xb1 = pack2(xa1[j], xa1[j]);
            acc[1][0] = fma2(xb1, wA.x, acc[1][0]);
            acc[1][1] = fma2(xb1, wA.y, acc[1][1]);
            acc[1][2] = fma2(xb1, wB.x, acc[1][2]);
            acc[1][3] = fma2(xb1, wB.y, acc[1][3]);

            u64t xb2 = pack2(xa2[j], xa2[j]);
            acc[2][0] = fma2(xb2, wA.x, acc[2][0]);
            acc[2][1] = fma2(xb2, wA.y, acc[2][1]);
            acc[2][2] = fma2(xb2, wB.x, acc[2][2]);
            acc[2][3] = fma2(xb2, wB.y, acc[2][3]);

            u64t xb3 = pack2(xa3[j], xa3[j]);
            acc[3][0] = fma2(xb3, wA.x, acc[3][0]);
            acc[3][1] = fma2(xb3, wA.y, acc[3][1]);
            acc[3][2] = fma2(xb3, wB.x, acc[3][2]);
            acc[3][3] = fma2(xb3, wB.y, acc[3][3]);
        }
    }

    // ---- combine quarter partials ----
    if (fq != 0) {
        float* rb = red + (fq - 1) * (ROWS_PER_BLOCK * ND);
        #pragma unroll
        for (int i = 0; i < 4; ++i) {
            float* rr = rb + (rloc + i) * ND;
            *(ulonglong2*)(rr + dA) = make_ulonglong2(acc[i][0], acc[i][1]);
            *(ulonglong2*)(rr + dB) = make_ulonglong2(acc[i][2], acc[i][3]);
        }
    }
    __syncthreads();

    if (fq == 0) {
        const u64t cinv = pack2(1.f / 256.f, 1.f / 256.f);
        const ulonglong2 mA = *(const ulonglong2*)(mb + dA);
        const ulonglong2 mB = *(const ulonglong2*)(mb + dB);

        #pragma unroll
        for (int i = 0; i < 4; ++i) {
            #pragma unroll
            for (int q = 0; q < 3; ++q) {
                const float* rr = red + q * (ROWS_PER_BLOCK * ND) + (rloc + i) * ND;
                ulonglong2 pA = *(const ulonglong2*)(rr + dA);
                ulonglong2 pB = *(const ulonglong2*)(rr + dB);
                acc[i][0] = add2(acc[i][0], pA.x);
                acc[i][1] = add2(acc[i][1], pA.y);
                acc[i][2] = add2(acc[i][2], pB.x);
                acc[i][3] = add2(acc[i][3], pB.y);
            }
            u64t r0 = fma2(acc[i][0], cinv, mA.x);
            u64t r1 = fma2(acc[i][1], cinv, mA.y);
            u64t r2 = fma2(acc[i][2], cinv, mB.x);
            u64t r3 = fma2(acc[i][3], cinv, mB.y);
            float* op = out + (size_t)(rbase + i) * ND;
            *(ulonglong2*)(op + dA) = make_ulonglong2(r0, r1);
            *(ulonglong2*)(op + dB) = make_ulonglong2(r2, r3);
        }
    }
}

extern "C" void kernel_launch(void* const* d_in, const int* in_sizes, int n_in,
                              void* d_out, int out_size)
{
    const float* x = (const float*)d_in[0];
    const float* W = (const float*)d_in[1];
    const float* b = (const float*)d_in[2];
    float* out = (float*)d_out;

    cudaFuncSetAttribute(nanembed_kernel,
                         cudaFuncAttributeMaxDynamicSharedMemorySize, SMEM_BYTES);
    nanembed_kernel<<<NBLOCKS, THREADS, SMEM_BYTES>>>(x, W, b, out);
}

// round 4
// speedup vs baseline: 1.9791x; 1.3821x over previous
#include <cuda_runtime.h>
#include <cstdint>

// out[n,d] = mean_f( x[n,f]*W[f,d] + b[f,d] ) = (x@W)[n,d]/256 + mean_f b[f,d]
// N=8192, F(K)=256, D(N)=64, f32 in/out, inputs finite.
//
// Tensor-core path via baseline PTX (sm_103 non-'a' safe): ldmatrix + 
// mma.sync.aligned.m16n8k16.row.col.f32.bf16.bf16.f32.
// Split x=x_hi+x_lo, W=W_hi+W_lo (bf16); accumulate hi*hi + hi*lo + lo*hi in f32.

typedef uint32_t u32;

#define NROWS  8192
#define NF     256
#define ND     64
#define TILE_M 32
#define THREADS 256
#define NBLOCKS (NROWS / TILE_M)   // 256

// padded bf16 pitches (bytes): conflict-free ldmatrix (16*i mod 128 distinct)
#define XPITCHB (264 * 2)   // 528 = (256+8) bf16
#define WPITCHB (72 * 2)    // 144 = (64+8) bf16

#define XH_OFF 0
#define XL_OFF (XH_OFF + TILE_M * XPITCHB)   // 16896
#define WH_OFF (XL_OFF + TILE_M * XPITCHB)   // 33792
#define WL_OFF (WH_OFF + NF * WPITCHB)       // 70656
#define MB_OFF (WL_OFF + NF * WPITCHB)       // 107520
#define SC_OFF (MB_OFF + 256)                // 107776 (256 float4 scratch)
#define SMEM_BYTES (SC_OFF + 4096)           // 111872

__device__ __forceinline__ u32 smem_u32(const void* p) {
    u32 a;
    asm("{ .reg .u64 t; cvta.to.shared.u64 t, %1; cvt.u32.u64 %0, t; }" : "=r"(a) : "l"(p));
    return a;
}

// pack (a,b) -> bf16x2 {lo=bf16(a), hi=bf16(b)}; lo-residual pair likewise
__device__ __forceinline__ void cvt_split(float a, float b, u32& hi, u32& lo) {
    asm("cvt.rn.bf16x2.f32 %0, %1, %2;" : "=r"(hi) : "f"(b), "f"(a));
    float ha = __uint_as_float(hi << 16);
    float hb = __uint_as_float(hi & 0xFFFF0000u);
    float ra = a - ha;
    float rb = b - hb;
    asm("cvt.rn.bf16x2.f32 %0, %1, %2;" : "=r"(lo) : "f"(rb), "f"(ra));
}

__device__ __forceinline__ void ldsm4(u32* r, u32 addr) {
    asm volatile("ldmatrix.sync.aligned.m8n8.x4.shared.b16 {%0,%1,%2,%3}, [%4];"
        : "=r"(r[0]), "=r"(r[1]), "=r"(r[2]), "=r"(r[3]) : "r"(addr));
}
__device__ __forceinline__ void ldsm4t(u32* r, u32 addr) {
    asm volatile("ldmatrix.sync.aligned.m8n8.x4.trans.shared.b16 {%0,%1,%2,%3}, [%4];"
        : "=r"(r[0]), "=r"(r[1]), "=r"(r[2]), "=r"(r[3]) : "r"(addr));
}
__device__ __forceinline__ void mma16816(float* c, const u32* a, u32 b0, u32 b1) {
    asm volatile(
        "mma.sync.aligned.m16n8k16.row.col.f32.bf16.bf16.f32 "
        "{%0,%1,%2,%3}, {%4,%5,%6,%7}, {%8,%9}, {%0,%1,%2,%3};"
        : "+f"(c[0]), "+f"(c[1]), "+f"(c[2]), "+f"(c[3])
        : "r"(a[0]), "r"(a[1]), "r"(a[2]), "r"(a[3]), "r"(b0), "r"(b1));
}

__global__ void __launch_bounds__(THREADS, 2)
nanembed_hmma_kernel(const float* __restrict__ x,
                     const float* __restrict__ W,
                     const float* __restrict__ b,
                     float* __restrict__ out)
{
    extern __shared__ char smem[];
    const u32 sb = smem_u32(smem);
    const int tid = threadIdx.x;

    // ---- convert x tile (32 x 256 f32) -> XH/XL bf16 padded ----
    {
        const float4* x4 = (const float4*)(x + (size_t)blockIdx.x * TILE_M * NF);
        #pragma unroll
        for (int i = 0; i < 8; ++i) {
            int idx = tid + THREADS * i;        // 0..2047
            int row = idx >> 6;                 // 64 float4 per row
            int c4  = idx & 63;
            float4 v = x4[idx];
            u32 h0, l0, h1, l1;
            cvt_split(v.x, v.y, h0, l0);
            cvt_split(v.z, v.w, h1, l1);
            u32 off = (u32)(row * XPITCHB + c4 * 8);
            asm volatile("st.shared.v2.b32 [%0], {%1, %2};"
                         :: "r"(sb + XH_OFF + off), "r"(h0), "r"(h1) : "memory");
            asm volatile("st.shared.v2.b32 [%0], {%1, %2};"
                         :: "r"(sb + XL_OFF + off), "r"(l0), "r"(l1) : "memory");
        }
    }

    // ---- convert W (256 x 64 f32, row=k, col=n) -> WH/WL bf16 padded ----
    {
        const float4* W4 = (const float4*)W;
        #pragma unroll
        for (int i = 0; i < 16; ++i) {
            int idx = tid + THREADS * i;        // 0..4095
            int row = idx >> 4;                 // 16 float4 per row
            int c4  = idx & 15;
            float4 v = W4[idx];
            u32 h0, l0, h1, l1;
            cvt_split(v.x, v.y, h0, l0);
            cvt_split(v.z, v.w, h1, l1);
            u32 off = (u32)(row * WPITCHB + c4 * 8);
            asm volatile("st.shared.v2.b32 [%0], {%1, %2};"
                         :: "r"(sb + WH_OFF + off), "r"(h0), "r"(h1) : "memory");
            asm volatile("st.shared.v2.b32 [%0], {%1, %2};"
                         :: "r"(sb + WL_OFF + off), "r"(l0), "r"(l1) : "memory");
        }
    }

    // ---- mb[d] = mean_f b[f][d] partial sums ----
    {
        float4* sc = (float4*)(smem + SC_OFF);
        const int qd = tid & 15;      // d-quad
        const int fr = tid >> 4;      // f-group of 16
        const float4* b4 = (const float4*)b;   // [256][16] float4
        float4 s = make_float4(0.f, 0.f, 0.f, 0.f);
        #pragma unroll
        for (int k = 0; k < 16; ++k) {
            float4 v = b4[(fr * 16 + k) * 16 + qd];
            s.x += v.x; s.y += v.y; s.z += v.z; s.w += v.w;
        }
        sc[tid] = s;
    }
    __syncthreads();
    if (tid < 16) {
        float4* sc = (float4*)(smem + SC_OFF);
        float4 m = make_float4(0.f, 0.f, 0.f, 0.f);
        #pragma unroll
        for (int g = 0; g < 16; ++g) {
            float4 v = sc[tid + 16 * g];
            m.x += v.x; m.y += v.y; m.z += v.z; m.w += v.w;
        }
        const float inv = 1.f / 256.f;
        m.x *= inv; m.y *= inv; m.z *= inv; m.w *= inv;
        ((float4*)(smem + MB_OFF))[tid] = m;
    }
    __syncthreads();

    // ---- mainloop: warp = 16 rows x 16 cols ----
    const int wid  = tid >> 5;
    const int lane = tid & 31;
    const int r0   = (wid & 1) * 16;     // row offset in tile
    const int n0   = (wid >> 1) * 16;    // col offset

    // ldmatrix source addresses
    // A (non-trans): lanes 0-7 rows r..r+7 (k lo), 8-15 rows+8, 16-23 k+8, 24-31 rows+8 k+8
    const u32 aRow = (u32)(r0 + (lane & 15));
    const u32 aCol = (u32)((lane >> 4) * 16);
    u32 aAddrH = sb + XH_OFF + aRow * XPITCHB + aCol;
    u32 aAddrL = aAddrH + (XL_OFF - XH_OFF);
    // B (trans): lanes 0-15 k rows 0..15 at n0, lanes 16-31 same rows at n0+8
    const u32 bRow = (u32)(lane & 15);
    const u32 bCol = (u32)(n0 * 2 + (lane >> 4) * 16);
    u32 bAddrH = sb + WH_OFF + bRow * WPITCHB + bCol;
    u32 bAddrL = bAddrH + (WL_OFF - WH_OFF);

    float acc0[4] = {0.f, 0.f, 0.f, 0.f};
    float acc1[4] = {0.f, 0.f, 0.f, 0.f};

    #pragma unroll
    for (int ki = 0; ki < 16; ++ki) {
        u32 ah[4], al[4], bh[4], bl[4];
        ldsm4 (ah, aAddrH + (u32)ki * 32);
        ldsm4 (al, aAddrL + (u32)ki * 32);
        ldsm4t(bh, bAddrH + (u32)ki * (16 * WPITCHB));
        ldsm4t(bl, bAddrL + (u32)ki * (16 * WPITCHB));
        // n-tile 0 (cols n0..n0+7)
        mma16816(acc0, ah, bh[0], bh[1]);
        mma16816(acc0, ah, bl[0], bl[1]);
        mma16816(acc0, al, bh[0], bh[1]);
        // n-tile 1 (cols n0+8..n0+15)
        mma16816(acc1, ah, bh[2], bh[3]);
        mma16816(acc1, ah, bl[2], bl[3]);
        mma16816(acc1, al, bh[2], bh[3]);
    }

    // ---- epilogue: D frag c0:(g,2t) c1:(g,2t+1) c2:(g+8,2t) c3:(g+8,2t+1) ----
    const int g = lane >> 2;
    const int t = lane & 3;
    const float* mb = (const float*)(smem + MB_OFF);
    const float inv = 1.f / 256.f;
    const int grow = blockIdx.x * TILE_M + r0 + g;

    {
        int col = n0 + 2 * t;
        float2 m = *(const float2*)(mb + col);
        float2 o0, o1;
        o0.x = fmaf(acc0[0], inv, m.x); o0.y = fmaf(acc0[1], inv, m.y);
        o1.x = fmaf(acc0[2], inv, m.x); o1.y = fmaf(acc0[3], inv, m.y);
        *(float2*)(out + (size_t)grow * ND + col) = o0;
        *(float2*)(out + (size_t)(grow + 8) * ND + col) = o1;
    }
    {
        int col = n0 + 8 + 2 * t;
        float2 m = *(const float2*)(mb + col);
        float2 o0, o1;
        o0.x = fmaf(acc1[0], inv, m.x); o0.y = fmaf(acc1[1], inv, m.y);
        o1.x = fmaf(acc1[2], inv, m.x); o1.y = fmaf(acc1[3], inv, m.y);
        *(float2*)(out + (size_t)grow * ND + col) = o0;
        *(float2*)(out + (size_t)(grow + 8) * ND + col) = o1;
    }
}

extern "C" void kernel_launch(void* const* d_in, const int* in_sizes, int n_in,
                              void* d_out, int out_size)
{
    const float* x = (const float*)d_in[0];
    const float* W = (const float*)d_in[1];
    const float* b = (const float*)d_in[2];
    float* out = (float*)d_out;

    cudaFuncSetAttribute(nanembed_hmma_kernel,
                         cudaFuncAttributeMaxDynamicSharedMemorySize, SMEM_BYTES);
    nanembed_hmma_kernel<<<NBLOCKS, THREADS, SMEM_BYTES>>>(x, W, b, out);
}